// round 2
// baseline (speedup 1.0000x reference)
#include <cuda_runtime.h>
#include <cstdint>

// Per-slot source map: token id >= 0 -> copy activations row,
// -1 -> keep old cache, -2 -> zero.
#define MAX_DM (8 * 32768)
__device__ int g_src[MAX_DM];

__device__ __forceinline__ int mask_at(const void* mask, int mtype, long i) {
    if (mtype == 1) return ((const int*)mask)[i] != 0;          // int32
    if (mtype == 2) return ((const float*)mask)[i] != 0.0f;     // float32
    return ((const uint8_t*)mask)[i] != 0;                      // uint8/bool
}

// One block per cache row d. Detects mask dtype, clears the src map, scans the
// mask row, scatters kept-token ids into ring slots, writes the tail outputs.
__global__ void setup_kernel(const void* __restrict__ mask,
                             const int* __restrict__ n_valid,
                             const int* __restrict__ index,
                             float* __restrict__ out_tail,
                             int D, int T, int M)
{
    const int d   = blockIdx.x;
    const int tid = threadIdx.x;
    const int NT  = blockDim.x;

    // ---- mask dtype probe over first D*T bytes (valid for all 3 dtypes) ----
    // float32: 1.0f has bytes 0x00 0x00 0x80 0x3f -> some byte > 1
    // int32  : 0/1 little-endian -> nonzero bytes only at pos%4==0
    // uint8  : 0/1 at every position -> nonzero at pos%4!=0 (w.h.p.)
    __shared__ int s_gt1, s_nzmod;
    if (tid == 0) { s_gt1 = 0; s_nzmod = 0; }
    __syncthreads();
    {
        const uint8_t* mb = (const uint8_t*)mask;
        const long nb = (long)D * T;
        int gt1 = 0, nzmod = 0;
        for (long i = tid; i < nb; i += NT) {
            uint8_t b = mb[i];
            if (b > 1) gt1 = 1;
            else if (b != 0 && (i & 3)) nzmod = 1;
        }
        if (gt1)   atomicOr(&s_gt1, 1);
        if (nzmod) atomicOr(&s_nzmod, 1);
    }

    int* src = g_src + (long)d * M;
    for (int i = tid; i < M; i += NT) src[i] = -1;
    __syncthreads();

    const int mtype = s_gt1 ? 2 : (s_nzmod ? 0 : 1);
    const long mbase = (long)d * T;

    const int chunk = (T + NT - 1) / NT;
    const int start = tid * chunk;

    int cnt = 0;
    for (int j = 0; j < chunk; ++j) {
        int t = start + j;
        if (t < T && mask_at(mask, mtype, mbase + t)) cnt++;
    }

    // Block exclusive scan over per-thread counts.
    const unsigned lane = tid & 31u;
    const unsigned wid  = tid >> 5;
    int v = cnt;
    #pragma unroll
    for (int off = 1; off < 32; off <<= 1) {
        int n = __shfl_up_sync(0xffffffffu, v, off);
        if (lane >= (unsigned)off) v += n;
    }
    __shared__ int warp_tot[32];
    __shared__ int warp_pref[33];
    if (lane == 31) warp_tot[wid] = v;
    __syncthreads();
    if (tid == 0) {
        int s = 0;
        int nw = (NT + 31) >> 5;
        for (int w = 0; w < nw; ++w) { warp_pref[w] = s; s += warp_tot[w]; }
        warp_pref[nw] = s;
    }
    __syncthreads();
    const int excl  = warp_pref[wid] + (v - cnt);
    const int total = warp_pref[(NT + 31) >> 5];

    const int idx0 = index[d];
    int rank = excl;
    for (int j = 0; j < chunk; ++j) {
        int t = start + j;
        if (t < T && mask_at(mask, mtype, mbase + t)) {
            int slot = idx0 + rank;            // rank < T < M, idx0 < M -> slot < 2M
            if (slot >= M) slot -= M;
            src[slot] = d * T + t;             // global token id
            rank++;
        }
    }

    if (tid == 0) {
        // First token masked -> offsets[0] = -1 -> slot (index-1) mod M is
        // set(0)+add(0) by the reference. Never collides with kept slots
        // since total < M.
        if (T > 0 && !mask_at(mask, mtype, mbase) && total < M) {
            int slot = idx0 - 1;
            if (slot < 0) slot += M;
            src[slot] = -2;
        }
        if (out_tail) {
            long nv = (long)n_valid[d] + total;
            if (nv > M) nv = M;
            out_tail[d]     = (float)nv;                     // new_n_valid
            out_tail[D + d] = (float)((idx0 + total) % M);   // new_index
        }
    }
}

// One block per cache slot-row (D*M blocks), blockDim = DIM/4 threads,
// one float4 per thread. Fully coalesced; branch is uniform per block.
__global__ void write_kernel(const float4* __restrict__ cache,
                             const float4* __restrict__ acts,
                             float4* __restrict__ out,
                             int DIM4)
{
    const long row = blockIdx.x;
    const int  s   = g_src[row];
    const long base = row * (long)DIM4 + threadIdx.x;

    float4 val;
    if (s >= 0)       val = acts[(long)s * DIM4 + threadIdx.x];
    else if (s == -1) val = cache[base];
    else              val = make_float4(0.f, 0.f, 0.f, 0.f);
    out[base] = val;
}

extern "C" void kernel_launch(void* const* d_in, const int* in_sizes, int n_in,
                              void* d_out, int out_size)
{
    const float* cache   = (const float*)d_in[0];
    const float* acts    = (const float*)d_in[1];
    const void*  mask    = (const void*)d_in[2];
    const int*   n_valid = (const int*)d_in[3];
    const int*   index   = (const int*)d_in[4];

    const int  D      = in_sizes[3];                      // 8
    const long DT     = (long)in_sizes[2];                // D*T
    const int  T      = (int)(DT / D);                    // 4096
    const int  DIM    = (int)((long)in_sizes[1] / DT);    // 768
    const long cacheN = (long)in_sizes[0];                // D*M*DIM
    const int  M      = (int)(cacheN / ((long)D * DIM));  // 32768
    const int  DIM4   = DIM / 4;

    float* out  = (float*)d_out;
    float* tail = ((long)out_size >= cacheN + 2L * D) ? (out + cacheN) : nullptr;

    setup_kernel<<<D, 256>>>(mask, n_valid, index, tail, D, T, M);

    const unsigned nrows = (unsigned)((long)D * M);
    write_kernel<<<nrows, DIM4>>>((const float4*)cache,
                                  (const float4*)acts,
                                  (float4*)out, DIM4);
}

// round 3
// speedup vs baseline: 1.2361x; 1.2361x over previous
#include <cuda_runtime.h>
#include <cstdint>

// Per-slot source map: token id >= 0 -> copy activations row,
// -1 -> keep old cache, -2 -> zero.
#define MAX_DM (8 * 32768)
__device__ int g_src[MAX_DM];

__device__ __forceinline__ int mask_at(const void* mask, int mtype, long i) {
    if (mtype == 1) return ((const int*)mask)[i] != 0;          // int32
    if (mtype == 2) return ((const float*)mask)[i] != 0.0f;     // float32
    return ((const uint8_t*)mask)[i] != 0;                      // uint8/bool
}

// One block per cache row d (1024 threads). Detects mask dtype, clears the src
// map, scans the mask row, scatters kept-token ids into ring slots, writes the
// tail outputs.
__global__ void setup_kernel(const void* __restrict__ mask,
                             const int* __restrict__ n_valid,
                             const int* __restrict__ index,
                             float* __restrict__ out_tail,
                             int D, int T, int M)
{
    const int d   = blockIdx.x;
    const int tid = threadIdx.x;
    const int NT  = blockDim.x;

    // ---- mask dtype probe over first D*T bytes (valid for all 3 dtypes) ----
    // float32: 1.0f has bytes 0x00 0x00 0x80 0x3f -> some byte > 1
    // int32  : 0/1 little-endian -> nonzero bytes only at pos%4==0
    // uint8  : 0/1 at every position -> nonzero at pos%4!=0 (w.h.p.)
    __shared__ int s_gt1, s_nzmod;
    if (tid == 0) { s_gt1 = 0; s_nzmod = 0; }
    __syncthreads();
    {
        const uint8_t* mb = (const uint8_t*)mask;
        const long nb = (long)D * T;
        int gt1 = 0, nzmod = 0;
        for (long i = tid; i < nb; i += NT) {
            uint8_t b = mb[i];
            if (b > 1) gt1 = 1;
            else if (b != 0 && (i & 3)) nzmod = 1;
        }
        if (gt1)   atomicOr(&s_gt1, 1);
        if (nzmod) atomicOr(&s_nzmod, 1);
    }

    int* src = g_src + (long)d * M;
    for (int i = tid; i < M; i += NT) src[i] = -1;
    __syncthreads();

    const int mtype = s_gt1 ? 2 : (s_nzmod ? 0 : 1);
    const long mbase = (long)d * T;

    const int chunk = (T + NT - 1) / NT;
    const int start = tid * chunk;

    int cnt = 0;
    for (int j = 0; j < chunk; ++j) {
        int t = start + j;
        if (t < T && mask_at(mask, mtype, mbase + t)) cnt++;
    }

    // Block exclusive scan over per-thread counts.
    const unsigned lane = tid & 31u;
    const unsigned wid  = tid >> 5;
    int v = cnt;
    #pragma unroll
    for (int off = 1; off < 32; off <<= 1) {
        int n = __shfl_up_sync(0xffffffffu, v, off);
        if (lane >= (unsigned)off) v += n;
    }
    __shared__ int warp_tot[32];
    __shared__ int warp_pref[33];
    if (lane == 31) warp_tot[wid] = v;
    __syncthreads();
    if (tid == 0) {
        int s = 0;
        int nw = (NT + 31) >> 5;
        for (int w = 0; w < nw; ++w) { warp_pref[w] = s; s += warp_tot[w]; }
        warp_pref[nw] = s;
    }
    __syncthreads();
    const int excl  = warp_pref[wid] + (v - cnt);
    const int total = warp_pref[(NT + 31) >> 5];

    const int idx0 = index[d];
    int rank = excl;
    for (int j = 0; j < chunk; ++j) {
        int t = start + j;
        if (t < T && mask_at(mask, mtype, mbase + t)) {
            int slot = idx0 + rank;            // rank < T < M, idx0 < M -> slot < 2M
            if (slot >= M) slot -= M;
            src[slot] = d * T + t;             // global token id
            rank++;
        }
    }

    if (tid == 0) {
        // First token masked -> offsets[0] = -1 -> slot (index-1) mod M is
        // set(0)+add(0) by the reference. Never collides with kept slots
        // since total < M.
        if (T > 0 && !mask_at(mask, mtype, mbase) && total < M) {
            int slot = idx0 - 1;
            if (slot < 0) slot += M;
            src[slot] = -2;
        }
        if (out_tail) {
            long nv = (long)n_valid[d] + total;
            if (nv > M) nv = M;
            out_tail[d]     = (float)nv;                     // new_n_valid
            out_tail[D + d] = (float)((idx0 + total) % M);   // new_index
        }
    }
}

// 4 cache slot-rows per block, blockDim = DIM/4, one float4 per thread per
// row. Branchless source-pointer select so the 4 LDG.128 issue back-to-back
// (MLP_p1 = 4). Streaming load/store hints: every byte is touched once.
__global__ void write_kernel4(const float4* __restrict__ cache,
                              const float4* __restrict__ acts,
                              float4* __restrict__ out,
                              int DIM4, int nrows)
{
    const int  t    = threadIdx.x;
    const long row0 = (long)blockIdx.x * 4;
    if (row0 + 3 < nrows) {
        const int s0 = g_src[row0 + 0];
        const int s1 = g_src[row0 + 1];
        const int s2 = g_src[row0 + 2];
        const int s3 = g_src[row0 + 3];

        const float4* p0 = (s0 >= 0 ? acts + (long)s0 * DIM4 : cache + (row0 + 0) * DIM4) + t;
        const float4* p1 = (s1 >= 0 ? acts + (long)s1 * DIM4 : cache + (row0 + 1) * DIM4) + t;
        const float4* p2 = (s2 >= 0 ? acts + (long)s2 * DIM4 : cache + (row0 + 2) * DIM4) + t;
        const float4* p3 = (s3 >= 0 ? acts + (long)s3 * DIM4 : cache + (row0 + 3) * DIM4) + t;

        float4 v0 = __ldcs(p0);
        float4 v1 = __ldcs(p1);
        float4 v2 = __ldcs(p2);
        float4 v3 = __ldcs(p3);

        const float4 z = make_float4(0.f, 0.f, 0.f, 0.f);
        if (s0 == -2) v0 = z;
        if (s1 == -2) v1 = z;
        if (s2 == -2) v2 = z;
        if (s3 == -2) v3 = z;

        float4* o = out + row0 * DIM4 + t;
        __stcs(o,            v0);
        __stcs(o + DIM4,     v1);
        __stcs(o + 2 * DIM4, v2);
        __stcs(o + 3 * DIM4, v3);
    } else {
        // tail (nrows not divisible by 4)
        for (long r = row0; r < nrows; ++r) {
            const int s = g_src[r];
            const float4* p = (s >= 0 ? acts + (long)s * DIM4 : cache + r * DIM4) + t;
            float4 v = __ldcs(p);
            if (s == -2) v = make_float4(0.f, 0.f, 0.f, 0.f);
            __stcs(out + r * DIM4 + t, v);
        }
    }
}

extern "C" void kernel_launch(void* const* d_in, const int* in_sizes, int n_in,
                              void* d_out, int out_size)
{
    const float* cache   = (const float*)d_in[0];
    const float* acts    = (const float*)d_in[1];
    const void*  mask    = (const void*)d_in[2];
    const int*   n_valid = (const int*)d_in[3];
    const int*   index   = (const int*)d_in[4];

    const int  D      = in_sizes[3];                      // 8
    const long DT     = (long)in_sizes[2];                // D*T
    const int  T      = (int)(DT / D);                    // 4096
    const int  DIM    = (int)((long)in_sizes[1] / DT);    // 768
    const long cacheN = (long)in_sizes[0];                // D*M*DIM
    const int  M      = (int)(cacheN / ((long)D * DIM));  // 32768
    const int  DIM4   = DIM / 4;

    float* out  = (float*)d_out;
    float* tail = ((long)out_size >= cacheN + 2L * D) ? (out + cacheN) : nullptr;

    setup_kernel<<<D, 1024>>>(mask, n_valid, index, tail, D, T, M);

    const int  nrows   = D * M;
    const unsigned nb  = (unsigned)((nrows + 3) / 4);
    write_kernel4<<<nb, DIM4>>>((const float4*)cache,
                                (const float4*)acts,
                                (float4*)out, DIM4, nrows);
}

// round 4
// speedup vs baseline: 1.2389x; 1.0022x over previous
#include <cuda_runtime.h>
#include <cstdint>

// Compact per-row maps (no clearing needed):
//   g_tok[d*T + rank] = global token id of the rank-th kept token in row d
//   g_idx0/g_total/g_zero: ring start, kept count, special zeroed slot (-1 if none)
#define MAX_D  64
#define MAX_DT (8 * 32768)
__device__ int g_tok[MAX_DT];
__device__ int g_idx0[MAX_D];
__device__ int g_total[MAX_D];
__device__ int g_zero[MAX_D];

__device__ __forceinline__ int mask_at(const void* mask, int mtype, long i) {
    if (mtype == 1) return ((const int*)mask)[i] != 0;          // int32
    if (mtype == 2) return ((const float*)mask)[i] != 0.0f;     // float32
    return ((const uint8_t*)mask)[i] != 0;                      // uint8/bool
}

// One block per cache row d (1024 threads). Detects mask dtype, scans the mask
// row, emits the compact rank->token list and per-row params + tail outputs.
__global__ void setup_kernel(const void* __restrict__ mask,
                             const int* __restrict__ n_valid,
                             const int* __restrict__ index,
                             float* __restrict__ out_tail,
                             int D, int T, int M)
{
    const int d   = blockIdx.x;
    const int tid = threadIdx.x;
    const int NT  = blockDim.x;

    // ---- mask dtype probe over first D*T bytes (valid for all 3 dtypes) ----
    // float32: 1.0f has bytes 0x00 0x00 0x80 0x3f -> some byte > 1
    // int32  : 0/1 little-endian -> nonzero bytes only at pos%4==0
    // uint8  : 0/1 at every position -> nonzero at pos%4!=0 (w.h.p.)
    __shared__ int s_gt1, s_nzmod;
    if (tid == 0) { s_gt1 = 0; s_nzmod = 0; }
    __syncthreads();
    {
        const uint8_t* mb = (const uint8_t*)mask;
        const long nb = (long)D * T;
        int gt1 = 0, nzmod = 0;
        for (long i = tid; i < nb; i += NT) {
            uint8_t b = mb[i];
            if (b > 1) gt1 = 1;
            else if (b != 0 && (i & 3)) nzmod = 1;
        }
        if (gt1)   atomicOr(&s_gt1, 1);
        if (nzmod) atomicOr(&s_nzmod, 1);
    }
    __syncthreads();

    const int mtype = s_gt1 ? 2 : (s_nzmod ? 0 : 1);
    const long mbase = (long)d * T;

    const int chunk = (T + NT - 1) / NT;
    const int start = tid * chunk;

    int cnt = 0;
    for (int j = 0; j < chunk; ++j) {
        int t = start + j;
        if (t < T && mask_at(mask, mtype, mbase + t)) cnt++;
    }

    // Block exclusive scan over per-thread counts.
    const unsigned lane = tid & 31u;
    const unsigned wid  = tid >> 5;
    int v = cnt;
    #pragma unroll
    for (int off = 1; off < 32; off <<= 1) {
        int n = __shfl_up_sync(0xffffffffu, v, off);
        if (lane >= (unsigned)off) v += n;
    }
    __shared__ int warp_tot[32];
    __shared__ int warp_pref[33];
    if (lane == 31) warp_tot[wid] = v;
    __syncthreads();
    if (tid == 0) {
        int s = 0;
        int nw = (NT + 31) >> 5;
        for (int w = 0; w < nw; ++w) { warp_pref[w] = s; s += warp_tot[w]; }
        warp_pref[nw] = s;
    }
    __syncthreads();
    const int excl  = warp_pref[wid] + (v - cnt);
    const int total = warp_pref[(NT + 31) >> 5];

    int rank = excl;
    int* tok = g_tok + (long)d * T;
    for (int j = 0; j < chunk; ++j) {
        int t = start + j;
        if (t < T && mask_at(mask, mtype, mbase + t)) {
            tok[rank++] = d * T + t;          // global token id, in rank order
        }
    }

    if (tid == 0) {
        const int idx0 = index[d];
        g_idx0[d]  = idx0;
        g_total[d] = total;
        // First token masked -> offsets[0] = -1 -> slot (index-1) mod M is
        // set(0)+add(0) by the reference. Never collides with kept slots
        // since total < M.
        int zs = -1;
        if (T > 0 && !mask_at(mask, mtype, mbase) && total < M) {
            zs = idx0 - 1;
            if (zs < 0) zs += M;
        }
        g_zero[d] = zs;
        if (out_tail) {
            long nv = (long)n_valid[d] + total;
            if (nv > M) nv = M;
            out_tail[d]     = (float)nv;                     // new_n_valid
            out_tail[D + d] = (float)((idx0 + total) % M);   // new_index
        }
    }
}

// 8 cache slot-rows per block, blockDim = DIM/4, one float4 per thread per
// row. Pointer selects are resolved first so the 8 LDG.128 issue back-to-back
// (MLP_p1 = 8). Streaming hints: every byte is touched once.
__global__ void write_kernel8(const float4* __restrict__ cache,
                              const float4* __restrict__ acts,
                              float4* __restrict__ out,
                              int DIM4, int M, int T, int nrows)
{
    const int  t    = threadIdx.x;
    const long row0 = (long)blockIdx.x * 8;

    if (row0 + 7 < nrows) {
        const float4* p[8];
        int zero_override[8];
        #pragma unroll
        for (int i = 0; i < 8; ++i) {
            const long r = row0 + i;
            const int  d = (int)(r / M);
            const int  s = (int)(r - (long)d * M);
            int rank = s - g_idx0[d];
            if (rank < 0) rank += M;
            const bool from_acts = rank < g_total[d];
            const int  tok = from_acts ? g_tok[(long)d * T + rank] : 0;
            p[i] = (from_acts ? acts + (long)tok * DIM4 : cache + r * DIM4) + t;
            zero_override[i] = (s == g_zero[d]);
        }

        float4 v[8];
        #pragma unroll
        for (int i = 0; i < 8; ++i) v[i] = __ldcs(p[i]);

        const float4 z = make_float4(0.f, 0.f, 0.f, 0.f);
        float4* o = out + row0 * DIM4 + t;
        #pragma unroll
        for (int i = 0; i < 8; ++i) {
            if (zero_override[i]) v[i] = z;
            __stcs(o + (long)i * DIM4, v[i]);
        }
    } else {
        for (long r = row0; r < nrows; ++r) {
            const int d = (int)(r / M);
            const int s = (int)(r - (long)d * M);
            int rank = s - g_idx0[d];
            if (rank < 0) rank += M;
            const bool from_acts = rank < g_total[d];
            const int  tok = from_acts ? g_tok[(long)d * T + rank] : 0;
            const float4* p = (from_acts ? acts + (long)tok * DIM4 : cache + r * DIM4) + t;
            float4 v = __ldcs(p);
            if (s == g_zero[d]) v = make_float4(0.f, 0.f, 0.f, 0.f);
            __stcs(out + r * DIM4 + t, v);
        }
    }
}

extern "C" void kernel_launch(void* const* d_in, const int* in_sizes, int n_in,
                              void* d_out, int out_size)
{
    const float* cache   = (const float*)d_in[0];
    const float* acts    = (const float*)d_in[1];
    const void*  mask    = (const void*)d_in[2];
    const int*   n_valid = (const int*)d_in[3];
    const int*   index   = (const int*)d_in[4];

    const int  D      = in_sizes[3];                      // 8
    const long DT     = (long)in_sizes[2];                // D*T
    const int  T      = (int)(DT / D);                    // 4096
    const int  DIM    = (int)((long)in_sizes[1] / DT);    // 768
    const long cacheN = (long)in_sizes[0];                // D*M*DIM
    const int  M      = (int)(cacheN / ((long)D * DIM));  // 32768
    const int  DIM4   = DIM / 4;

    float* out  = (float*)d_out;
    float* tail = ((long)out_size >= cacheN + 2L * D) ? (out + cacheN) : nullptr;

    setup_kernel<<<D, 1024>>>(mask, n_valid, index, tail, D, T, M);

    const int nrows   = D * M;
    const unsigned nb = (unsigned)((nrows + 7) / 8);
    write_kernel8<<<nb, DIM4>>>((const float4*)cache,
                                (const float4*)acts,
                                (float4*)out, DIM4, M, T, nrows);
}